// round 7
// baseline (speedup 1.0000x reference)
#include <cuda_runtime.h>
#include <cuda_bf16.h>
#include <cstdint>

#define B_    64
#define T_    512
#define F_    1024
#define H_    52
#define HP_   56
#define START_ 50
#define STOP_  51
#define BT_   (B_ * T_)

__device__ float g_emitT[(size_t)B_ * H_ * T_]; // emit transposed [b][h][t]
__device__ float g_diff[B_];

// ---------- packed fp32x2 helpers ----------
__device__ __forceinline__ unsigned long long pk2(float lo, float hi) {
    unsigned long long d;
    asm("mov.b64 %0, {%1, %2};" : "=l"(d) : "r"(__float_as_uint(lo)), "r"(__float_as_uint(hi)));
    return d;
}
__device__ __forceinline__ void upk2(unsigned long long v, float& lo, float& hi) {
    unsigned int a, b;
    asm("mov.b64 {%0, %1}, %2;" : "=r"(a), "=r"(b) : "l"(v));
    lo = __uint_as_float(a); hi = __uint_as_float(b);
}
__device__ __forceinline__ unsigned long long fma2(unsigned long long a, unsigned long long b,
                                                   unsigned long long c) {
    unsigned long long d;
    asm("fma.rn.f32x2 %0, %1, %2, %3;" : "=l"(d) : "l"(a), "l"(b), "l"(c));
    return d;
}
__device__ __forceinline__ unsigned long long add2(unsigned long long a, unsigned long long b) {
    unsigned long long d;
    asm("add.rn.f32x2 %0, %1, %2;" : "=l"(d) : "l"(a), "l"(b));
    return d;
}
__device__ __forceinline__ uint32_t smem_u32(const void* p) {
    uint32_t a;
    asm("{ .reg .u64 t; cvta.to.shared.u64 t, %1; cvt.u32.u64 %0, t; }" : "=r"(a) : "l"(p));
    return a;
}
__device__ __forceinline__ void cpasync8(uint32_t dst, const float* src) {
    asm volatile("cp.async.ca.shared.global [%0], [%1], 8;" :: "r"(dst), "l"(src));
}

// ============================================================
// Kernel 1: emit = features @ W^T + b   (M=32768, N=52, K=1024)
// Same 4-row x 7-pair tile as the 91us config, but features come in
// via cp.async (no fv staging regs) => regs<=128 => 2 CTAs/SM.
// sF layout [row][34] (8B aligned rows, 2-way LDS conflict).
// One __syncthreads + one wait_group per 32-k chunk.
// ============================================================
#define SF_ST 34
#define SF_BUFV (256 * SF_ST)     // 8704 floats
#define SW_ST 58
#define SW_BUFV (32 * SW_ST)      // 1856 floats
#define GEMM_SMEM_BYTES ((2 * SF_BUFV + 2 * SW_BUFV) * 4)   // 84480 B

__global__ void __launch_bounds__(256, 2)
emit_gemm_kernel(const float* __restrict__ feat, const float* __restrict__ W,
                 const float* __restrict__ bias) {
    extern __shared__ __align__(16) float smem[];
    float* sF = smem;                 // 2 x [256][34]
    float* sW = smem + 2 * SF_BUFV;   // 2 x [32][58]
    const uint32_t sfu = smem_u32(smem);

    const int tid = threadIdx.x;
    const int cg = tid >> 6;       // 0..3  (14 cols each)
    const int rt = tid & 63;       // 0..63
    const int blockRow = blockIdx.x * 256;

    const int rgrp = tid >> 4;     // 0..15
    const int jj   = tid & 15;     // 0..15 (k-pair)
    const int wkk  = tid & 31;
    const int whb  = tid >> 5;     // 0..7

    unsigned long long acc[4][7];
#pragma unroll
    for (int r = 0; r < 4; r++)
#pragma unroll
        for (int j = 0; j < 7; j++) acc[r][j] = 0ULL;

    float wv[7];

    auto cpF = [&](int c, int buf) {
        const int k0 = c * 32;
        const float* src = &feat[(size_t)(blockRow + rgrp) * F_ + k0 + 2 * jj];
        const uint32_t dst = sfu + (uint32_t)(buf * SF_BUFV + rgrp * SF_ST + 2 * jj) * 4;
#pragma unroll
        for (int i = 0; i < 16; i++) {   // rows rgrp + 16*i
            cpasync8(dst + (uint32_t)(16 * i * SF_ST) * 4, src + (size_t)(16 * i) * F_);
        }
        asm volatile("cp.async.commit_group;" ::: "memory");
    };
    auto ldW = [&](int c) {
        const int k0 = c * 32;
#pragma unroll
        for (int it = 0; it < 7; it++) {
            int hh = whb + it * 8;
            wv[it] = (hh < H_) ? W[(size_t)hh * F_ + k0 + wkk] : 0.0f;
        }
    };
    auto stW = [&](int buf) {
        float* w = sW + buf * SW_BUFV;
#pragma unroll
        for (int it = 0; it < 7; it++) w[wkk * SW_ST + whb + it * 8] = wv[it];
    };
    auto compute = [&](int buf) {
        const float* fbase = sF + buf * SF_BUFV;
        const float* wbase = sW + buf * SW_BUFV;
#pragma unroll 4
        for (int kk = 0; kk < 32; kk++) {
            float f0 = fbase[rt * SF_ST + kk];
            float f1 = fbase[(rt + 64) * SF_ST + kk];
            float f2 = fbase[(rt + 128) * SF_ST + kk];
            float f3 = fbase[(rt + 192) * SF_ST + kk];
            unsigned long long p0 = pk2(f0, f0);
            unsigned long long p1 = pk2(f1, f1);
            unsigned long long p2 = pk2(f2, f2);
            unsigned long long p3 = pk2(f3, f3);
#pragma unroll
            for (int j = 0; j < 7; j++) {
                unsigned long long w2 = *reinterpret_cast<const unsigned long long*>(
                    &wbase[kk * SW_ST + cg * 14 + 2 * j]);
                acc[0][j] = fma2(p0, w2, acc[0][j]);
                acc[1][j] = fma2(p1, w2, acc[1][j]);
                acc[2][j] = fma2(p2, w2, acc[2][j]);
                acc[3][j] = fma2(p3, w2, acc[3][j]);
            }
        }
    };

    // prologue
    cpF(0, 0);
    ldW(0);
    stW(0);
    ldW(1);                      // wv = W(1)
    asm volatile("cp.async.wait_group 0;" ::: "memory");
    __syncthreads();

#pragma unroll 1
    for (int c = 0; c < 32; c++) {
        const int buf = c & 1;
        if (c + 1 < 32) {
            cpF(c + 1, buf ^ 1);     // covered by compute(c)
            stW(buf ^ 1);            // wv holds W(c+1)
        }
        if (c + 2 < 32) ldW(c + 2);
        compute(buf);
        asm volatile("cp.async.wait_group 0;" ::: "memory");
        __syncthreads();
    }

    // epilogue: + bias, store transposed
#pragma unroll
    for (int r = 0; r < 4; r++) {
        int row = blockRow + rt + r * 64;
        int b = row >> 9;
        int t = row & 511;
        size_t bbase = (size_t)b * (H_ * T_);
#pragma unroll
        for (int j = 0; j < 7; j++) {
            int col = cg * 14 + 2 * j;
            if (col + 1 < H_) {
                float lo, hi;
                upk2(acc[r][j], lo, hi);
                lo += __ldg(&bias[col]);
                hi += __ldg(&bias[col + 1]);
                g_emitT[bbase + (size_t)col * T_ + t] = lo;
                g_emitT[bbase + (size_t)(col + 1) * T_ + t] = hi;
            }
        }
    }
}

// ============================================================
// Kernel 2: CRF forward — 4 warps per batch, source-split matvec.
// Same structure as R6 (best scan so far) with conflict-free
// partial-exchange strides (stride 10 floats = odd 8B stride).
// ============================================================
__global__ void __launch_bounds__(128, 1)
crf_scan_kernel(const float* __restrict__ transition, const float* __restrict__ masks,
                const int* __restrict__ tags) {
    const int b = blockIdx.x;
    const int tid = threadIdx.x;
    const int w = tid >> 5;
    const int lane = tid & 31;
    const int base = b * T_;
    const unsigned FULL = 0xFFFFFFFFu;

    __shared__ __align__(16) float p2[2 * HP_];        // splat pairs
    __shared__ __align__(16) float part[2][28][10];    // [parity][dp][w*2], stride 40B
    __shared__ float rslot;
    __shared__ float redsm[12];

    const float* embB = &g_emitT[(size_t)b * (H_ * T_)];

    // ---- gold score partials ----
    float gold = 0.0f, msum = 0.0f;
    for (int t = tid; t < T_; t += 128) {
        float mk = masks[base + t];
        int tg = tags[base + t];
        int pv = (t == 0) ? START_ : tags[base + t - 1];
        gold += mk * (embB[(size_t)tg * T_ + t] + transition[tg * H_ + pv]);
        msum += mk;
    }
#pragma unroll
    for (int s = 16; s > 0; s >>= 1) {
        gold += __shfl_xor_sync(FULL, gold, s);
        msum += __shfl_xor_sync(FULL, msum, s);
    }
    if (lane == 0) { redsm[w] = gold; redsm[4 + w] = msum; }

    // ---- phase-A constants ----
    unsigned long long E2[14];
    const int dp = lane;
    if (lane < 28) {
        int d0 = 2 * dp, d1 = d0 + 1;
#pragma unroll
        for (int k = 0; k < 14; k++) {
            int src = 14 * w + k;
            float v0 = (d0 < H_ && src < H_) ? __expf(transition[d0 * H_ + src]) : 0.0f;
            float v1 = (d1 < H_ && src < H_) ? __expf(transition[d1 * H_ + src]) : 0.0f;
            E2[k] = pk2(v0, v1);
        }
    }

    // ---- phase-B state ----
    const int dpp = 7 * w + lane;
    const int pd0 = 2 * dpp, pd1 = pd0 + 1;
    float po0 = (pd0 == START_) ? 1.0f : 0.0f;
    float po1 = (pd1 == START_) ? 1.0f : 0.0f;
    float offset = 0.0f;
    const int c0 = (pd0 < H_) ? pd0 : 0;
    const int c1 = (pd1 < H_) ? pd1 : 0;
    const float* e0p = embB + (size_t)c0 * T_;
    const float* e1p = embB + (size_t)c1 * T_;
    const float4* m4 = reinterpret_cast<const float4*>(&masks[base]);

    float eC0[4], eC1[4], mkArr[4];
    if (lane < 7) {
        float4 a = *reinterpret_cast<const float4*>(e0p);
        float4 c = *reinterpret_cast<const float4*>(e1p);
        eC0[0] = __expf(a.x); eC0[1] = __expf(a.y); eC0[2] = __expf(a.z); eC0[3] = __expf(a.w);
        eC1[0] = __expf(c.x); eC1[1] = __expf(c.y); eC1[2] = __expf(c.z); eC1[3] = __expf(c.w);
        float4 m = m4[0];
        mkArr[0] = m.x; mkArr[1] = m.y; mkArr[2] = m.z; mkArr[3] = m.w;
    }

    if (tid < HP_) {
        float v = (tid == START_) ? 1.0f : 0.0f;
        p2[2 * tid] = v; p2[2 * tid + 1] = v;
    }
    __syncthreads();

    const float* pw = &p2[28 * w];

    const int NB = T_ / 4;
    for (int tb = 0; tb < NB; tb++) {
        float4 l0, l1, lm;
        const bool hv = (tb + 1 < NB);
        if (lane < 7 && hv) {
            l0 = *reinterpret_cast<const float4*>(e0p + (tb + 1) * 4);
            l1 = *reinterpret_cast<const float4*>(e1p + (tb + 1) * 4);
            lm = m4[tb + 1];
        }

#pragma unroll
        for (int s = 0; s < 4; s++) {
            const int par = s & 1;
            if (lane < 28) {
                const ulonglong2* u = reinterpret_cast<const ulonglong2*>(pw);
                ulonglong2 u0 = u[0], u1 = u[1], u2 = u[2];
                ulonglong2 u3 = u[3], u4 = u[4], u5 = u[5], u6 = u[6];
                unsigned long long a0 = 0ULL, a1 = 0ULL, a2 = 0ULL, a3 = 0ULL;
                a0 = fma2(E2[0],  u0.x, a0); a1 = fma2(E2[1],  u0.y, a1);
                a2 = fma2(E2[2],  u1.x, a2); a3 = fma2(E2[3],  u1.y, a3);
                a0 = fma2(E2[4],  u2.x, a0); a1 = fma2(E2[5],  u2.y, a1);
                a2 = fma2(E2[6],  u3.x, a2); a3 = fma2(E2[7],  u3.y, a3);
                a0 = fma2(E2[8],  u4.x, a0); a1 = fma2(E2[9],  u4.y, a1);
                a2 = fma2(E2[10], u5.x, a2); a3 = fma2(E2[11], u5.y, a3);
                a0 = fma2(E2[12], u6.x, a0); a1 = fma2(E2[13], u6.y, a1);
                unsigned long long s2 = add2(add2(a0, a1), add2(a2, a3));
                *reinterpret_cast<unsigned long long*>(&part[par][dp][2 * w]) = s2;
            }
            __syncthreads();
            if (lane < 7) {
                const float* pr = &part[par][dpp][0];
                unsigned long long q0 = *reinterpret_cast<const unsigned long long*>(pr);
                unsigned long long q1 = *reinterpret_cast<const unsigned long long*>(pr + 2);
                unsigned long long q2 = *reinterpret_cast<const unsigned long long*>(pr + 4);
                unsigned long long q3 = *reinterpret_cast<const unsigned long long*>(pr + 6);
                unsigned long long s2 = add2(add2(q0, q1), add2(q2, q3));
                float S0, S1;
                upk2(s2, S0, S1);
                bool on = (mkArr[s] > 0.5f);
                float n0 = on ? S0 * eC0[s] : po0;
                float n1 = on ? S1 * eC1[s] : po1;
                if (s == 0 && tb) {
                    float r = rslot;
                    float ri = 1.0f / r;
                    offset += __logf(r);
                    n0 *= ri; n1 *= ri;
                }
                float4 sp = make_float4(n0, n0, n1, n1);
                *reinterpret_cast<float4*>(&p2[4 * dpp]) = sp;
                if (tid == 0 && s == 3) rslot = n0;
                po0 = n0; po1 = n1;
            }
            __syncwarp();
        }

        if (lane < 7 && hv) {
            eC0[0] = __expf(l0.x); eC0[1] = __expf(l0.y); eC0[2] = __expf(l0.z); eC0[3] = __expf(l0.w);
            eC1[0] = __expf(l1.x); eC1[1] = __expf(l1.y); eC1[2] = __expf(l1.z); eC1[3] = __expf(l1.w);
            mkArr[0] = lm.x; mkArr[1] = lm.y; mkArr[2] = lm.z; mkArr[3] = lm.w;
        }
    }

    // ---- final reduction ----
    float term = 0.0f;
    if (lane < 7) {
        float es0 = (pd0 < H_) ? __expf(transition[STOP_ * H_ + pd0]) : 0.0f;
        float es1 = (pd1 < H_) ? __expf(transition[STOP_ * H_ + pd1]) : 0.0f;
        term = po0 * es0 + po1 * es1;
    }
#pragma unroll
    for (int s = 16; s > 0; s >>= 1) term += __shfl_xor_sync(FULL, term, s);
    if (lane == 0) redsm[8 + w] = term;
    __syncthreads();
    if (tid == 0) {
        float goldv = redsm[0] + redsm[1] + redsm[2] + redsm[3];
        float msumv = redsm[4] + redsm[5] + redsm[6] + redsm[7];
        float tsum  = redsm[8] + redsm[9] + redsm[10] + redsm[11];
        int lp = (int)(msumv + 0.5f);
        int lt = (lp > 0) ? tags[base + lp - 1] : START_;
        goldv += transition[STOP_ * H_ + lt];
        g_diff[b] = offset + __logf(tsum) - goldv;
    }
}

// ============================================================
// Kernel 3: mean over batches
// ============================================================
__global__ void __launch_bounds__(64)
finalize_kernel(float* __restrict__ out) {
    __shared__ float red[64];
    int tid = threadIdx.x;
    red[tid] = g_diff[tid];
    __syncthreads();
    for (int s = 32; s > 0; s >>= 1) { if (tid < s) red[tid] += red[tid + s]; __syncthreads(); }
    if (tid == 0) out[0] = red[0] * (1.0f / (float)B_);
}

// ============================================================
// launch
// ============================================================
extern "C" void kernel_launch(void* const* d_in, const int* in_sizes, int n_in,
                              void* d_out, int out_size) {
    const float* feat  = (const float*)d_in[0];
    const float* W     = (const float*)d_in[1];
    const float* bias  = (const float*)d_in[2];
    const float* trans = (const float*)d_in[3];
    const float* masks = (const float*)d_in[4];
    const int*   tags  = (const int*)d_in[5];
    float* out = (float*)d_out;

    cudaFuncSetAttribute(emit_gemm_kernel,
                         cudaFuncAttributeMaxDynamicSharedMemorySize, GEMM_SMEM_BYTES);

    emit_gemm_kernel<<<128, 256, GEMM_SMEM_BYTES>>>(feat, W, bias);
    crf_scan_kernel<<<B_, 128>>>(trans, masks, tags);
    finalize_kernel<<<1, 64>>>(out);
}